// round 7
// baseline (speedup 1.0000x reference)
#include <cuda_runtime.h>
#include <cuda_bf16.h>
#include <cstdint>

#define BB 4
#define TT 4096
#define DD 768
#define HH 64
#define BT (BB*TT)
#define NSPLIT 4

// Scratch
__device__ float  g_Q[BT * HH];
__device__ float  g_K[BT * HH];
__device__ float  g_V[BT * HH];
__device__ float2 g_Wsp[DD * 192];          // W (Q|K|V) split into (tf32 hi, lo)
__device__ float  g_pO[NSPLIT * BT * HH];   // split-kv partial O (unnormalized)
__device__ float  g_pm[NSPLIT * BT];        // partial running max
__device__ float  g_pl[NSPLIT * BT];        // partial denom

// ---------------------------------------------------------------------------
// tf32 helpers
// ---------------------------------------------------------------------------
__device__ __forceinline__ uint32_t f2tf(float f) {
    uint32_t u;
    asm("cvt.rna.tf32.f32 %0, %1;" : "=r"(u) : "f"(f));
    return u;
}
__device__ __forceinline__ float tf32f(float f) {
    return __uint_as_float(f2tf(f));
}

__device__ __forceinline__ void mma_tf32(float d[4], const uint32_t a[4],
                                         uint32_t b0, uint32_t b1) {
    asm volatile(
        "mma.sync.aligned.m16n8k8.row.col.f32.tf32.tf32.f32 "
        "{%0,%1,%2,%3}, {%4,%5,%6,%7}, {%8,%9}, {%0,%1,%2,%3};"
        : "+f"(d[0]), "+f"(d[1]), "+f"(d[2]), "+f"(d[3])
        : "r"(a[0]), "r"(a[1]), "r"(a[2]), "r"(a[3]), "r"(b0), "r"(b1));
}

// ---------------------------------------------------------------------------
// Kernel 0: split W = [Wq|Wk|Wv] into (hi, lo) tf32 pair.
// ---------------------------------------------------------------------------
__global__ __launch_bounds__(256) void prep_w(
    const float* __restrict__ Wq, const float* __restrict__ Wk,
    const float* __restrict__ Wv)
{
    int i = blockIdx.x * 256 + threadIdx.x;
    if (i >= DD * 192) return;
    int k = i / 192, n = i % 192;
    float v = (n < 64) ? Wq[k * 64 + n]
            : (n < 128) ? Wk[k * 64 + n - 64]
            : Wv[k * 64 + n - 128];
    float hi = tf32f(v);
    float lo = tf32f(v - hi);
    g_Wsp[i] = make_float2(hi, lo);
}

// ---------------------------------------------------------------------------
// Kernel 1: QKV projection, tensor cores, 3-term tf32 split, sw-pipelined.
// (unchanged from R6 — known good)
// ---------------------------------------------------------------------------
__global__ __launch_bounds__(256) void qkv_mma(const float* __restrict__ x)
{
    __shared__ float  xs[128 * 36];
    __shared__ float4 wf[4 * 12 * 33];

    const int tid = threadIdx.x;
    const int w   = tid >> 5;
    const int l   = tid & 31;
    const int mg  = w >> 1;
    const int ng  = w & 1;
    const int row0 = (blockIdx.x >> 1) * 128;
    const int n0   = (blockIdx.x & 1) * 96;

    float acc[2][6][4];
    #pragma unroll
    for (int mt = 0; mt < 2; mt++)
        #pragma unroll
        for (int nb = 0; nb < 6; nb++)
            acc[mt][nb][0] = acc[mt][nb][1] = acc[mt][nb][2] = acc[mt][nb][3] = 0.0f;

    float4 px[4];
    float2 pw[12];

    #pragma unroll
    for (int t = 0; t < 4; t++) {
        int f  = tid + t * 256;
        int r  = f >> 3;
        int c4 = (f & 7) * 4;
        px[t] = *(const float4*)&x[(size_t)(row0 + r) * DD + c4];
    }
    #pragma unroll
    for (int t = 0; t < 12; t++) {
        int i  = tid + t * 256;
        int kk = i / 96;
        int nn = i % 96;
        pw[t] = g_Wsp[(size_t)kk * 192 + n0 + nn];
    }

    for (int k0 = 0; k0 < DD; k0 += 32) {
        #pragma unroll
        for (int t = 0; t < 4; t++) {
            int f  = tid + t * 256;
            int r  = f >> 3;
            int c4 = (f & 7) * 4;
            *(float4*)&xs[r * 36 + c4] = px[t];
        }
        #pragma unroll
        for (int t = 0; t < 12; t++) {
            int i  = tid + t * 256;
            int kk = i / 96;
            int nn = i % 96;
            int kb   = kk >> 3, kr = kk & 7;
            int slot = kr >> 2;
            int nb   = nn >> 3;
            int lane = ((nn & 7) << 2) | (kr & 3);
            float* p = (float*)&wf[(kb * 12 + nb) * 33 + lane];
            p[slot]     = pw[t].x;
            p[2 + slot] = pw[t].y;
        }
        __syncthreads();

        if (k0 + 32 < DD) {
            #pragma unroll
            for (int t = 0; t < 4; t++) {
                int f  = tid + t * 256;
                int r  = f >> 3;
                int c4 = (f & 7) * 4;
                px[t] = *(const float4*)&x[(size_t)(row0 + r) * DD + k0 + 32 + c4];
            }
            #pragma unroll
            for (int t = 0; t < 12; t++) {
                int i  = tid + t * 256;
                int kk = i / 96;
                int nn = i % 96;
                pw[t] = g_Wsp[(size_t)(k0 + 32 + kk) * 192 + n0 + nn];
            }
        }

        #pragma unroll
        for (int kb = 0; kb < 4; kb++) {
            uint32_t ahi[2][4], alo[2][4];
            #pragma unroll
            for (int mt = 0; mt < 2; mt++) {
                const int rA = mg * 32 + mt * 16 + (l >> 2);
                const int cA = kb * 8 + (l & 3);
                float a0 = xs[rA * 36 + cA];
                float a1 = xs[(rA + 8) * 36 + cA];
                float a2 = xs[rA * 36 + cA + 4];
                float a3 = xs[(rA + 8) * 36 + cA + 4];
                ahi[mt][0] = f2tf(a0); alo[mt][0] = f2tf(a0 - __uint_as_float(ahi[mt][0]));
                ahi[mt][1] = f2tf(a1); alo[mt][1] = f2tf(a1 - __uint_as_float(ahi[mt][1]));
                ahi[mt][2] = f2tf(a2); alo[mt][2] = f2tf(a2 - __uint_as_float(ahi[mt][2]));
                ahi[mt][3] = f2tf(a3); alo[mt][3] = f2tf(a3 - __uint_as_float(ahi[mt][3]));
            }
            #pragma unroll
            for (int nb = 0; nb < 6; nb++) {
                float4 q = wf[(kb * 12 + ng * 6 + nb) * 33 + l];
                uint32_t bh0 = __float_as_uint(q.x), bh1 = __float_as_uint(q.y);
                uint32_t bl0 = __float_as_uint(q.z), bl1 = __float_as_uint(q.w);
                #pragma unroll
                for (int mt = 0; mt < 2; mt++) {
                    mma_tf32(acc[mt][nb], ahi[mt], bh0, bh1);
                    mma_tf32(acc[mt][nb], ahi[mt], bl0, bl1);
                    mma_tf32(acc[mt][nb], alo[mt], bh0, bh1);
                }
            }
        }
        __syncthreads();
    }

    #pragma unroll
    for (int mt = 0; mt < 2; mt++) {
        #pragma unroll
        for (int nb = 0; nb < 6; nb++) {
            const int rowa  = row0 + mg * 32 + mt * 16 + (l >> 2);
            const int nglob = n0 + ng * 48 + nb * 8 + (l & 3) * 2;
            const int mat   = nglob >> 6;
            const int col   = nglob & 63;
            float* g = (mat == 0) ? g_Q : (mat == 1) ? g_K : g_V;
            *(float2*)&g[(size_t)rowa * HH + col] =
                make_float2(acc[mt][nb][0], acc[mt][nb][1]);
            *(float2*)&g[(size_t)(rowa + 8) * HH + col] =
                make_float2(acc[mt][nb][2], acc[mt][nb][3]);
        }
    }
}

// ---------------------------------------------------------------------------
// Kernel 2: causal flash attention, tensor cores, split-kv (4),
// DOUBLE-BUFFERED fragment smem: one __syncthreads per tile.
// ---------------------------------------------------------------------------
#define FSTR 66
#define PSTR 68
#define KVBUF (2 * 64 * FSTR)          // one K+V buffer pair (floats)

__device__ __forceinline__ void stage_kv(float* __restrict__ Ksf,
                                         float* __restrict__ Vsf,
                                         const float4* pk, const float4* pv,
                                         int jj0, int hh0)
{
    #pragma unroll
    for (int i = 0; i < 8; i++) {
        const int j  = jj0 + i * 8;
        const int h0 = hh0;
        {
            const int frK  = ((h0 >> 3) << 3) + (j >> 3);
            const int slot = (h0 >> 2) & 1;
            const int lb   = (j & 7) << 2;
            float* p = &Ksf[frK * FSTR + slot];
            p[(lb + 0) * 2] = __uint_as_float(f2tf(pk[i].x));
            p[(lb + 1) * 2] = __uint_as_float(f2tf(pk[i].y));
            p[(lb + 2) * 2] = __uint_as_float(f2tf(pk[i].z));
            p[(lb + 3) * 2] = __uint_as_float(f2tf(pk[i].w));
        }
        {
            const int frV  = ((j >> 3) << 3) + (h0 >> 3);
            const int slot = (j >> 2) & 1;
            const int h7   = h0 & 7;
            const int j3   = j & 3;
            float* p = &Vsf[frV * FSTR + slot];
            p[((h7 + 0) * 4 + j3) * 2] = pv[i].x;
            p[((h7 + 1) * 4 + j3) * 2] = pv[i].y;
            p[((h7 + 2) * 4 + j3) * 2] = pv[i].z;
            p[((h7 + 3) * 4 + j3) * 2] = pv[i].w;
        }
    }
}

__global__ __launch_bounds__(128) void attn_kernel()
{
    extern __shared__ float sm[];
    float* Ps = sm + 2 * KVBUF;

    const int tid = threadIdx.x;
    const int w   = tid >> 5;
    const int l   = tid & 31;
    const int r   = l >> 2;
    const int c   = l & 3;

    const int bid = blockIdx.x;
    const int qt  = 63 - (bid >> 4);       // heavy q-tiles first
    const int b   = (bid >> 2) & 3;
    const int s   = bid & 3;
    const int q0  = qt * 64;
    const size_t base = (size_t)b * TT * HH;

    const int nt    = qt + 1;
    const int chunk = (nt + NSPLIT - 1) >> 2;
    const int ktbeg = min(s * chunk, nt);
    const int ktend = min(ktbeg + chunk, nt);

    const int rowg  = q0 + w * 16 + r;
    const int rowg8 = rowg + 8;

    const int jj0 = tid >> 4;
    const int hh0 = (tid & 15) << 2;

    float o[8][4];
    #pragma unroll
    for (int hb = 0; hb < 8; hb++)
        o[hb][0] = o[hb][1] = o[hb][2] = o[hb][3] = 0.0f;
    float mR = -1.0e30f, mR8 = -1.0e30f, lR = 0.0f, lR8 = 0.0f;

    if (ktbeg < ktend) {
        // Q fragments in registers (scaled by 1/8, tf32-rounded)
        uint32_t qf[8][4];
        #pragma unroll
        for (int kb = 0; kb < 8; kb++) {
            qf[kb][0] = f2tf(0.125f * g_Q[base + (size_t)rowg  * HH + kb * 8 + c]);
            qf[kb][1] = f2tf(0.125f * g_Q[base + (size_t)rowg8 * HH + kb * 8 + c]);
            qf[kb][2] = f2tf(0.125f * g_Q[base + (size_t)rowg  * HH + kb * 8 + c + 4]);
            qf[kb][3] = f2tf(0.125f * g_Q[base + (size_t)rowg8 * HH + kb * 8 + c + 4]);
        }

        float4 pk[8], pv[8];
        #pragma unroll
        for (int i = 0; i < 8; i++) {
            const int j = jj0 + i * 8;
            const size_t g = base + (size_t)(ktbeg * 64 + j) * HH + hh0;
            pk[i] = *(const float4*)&g_K[g];
            pv[i] = *(const float4*)&g_V[g];
        }
        stage_kv(sm, sm + 64 * FSTR, pk, pv, jj0, hh0);
        __syncthreads();

        int cur = 0;
        for (int kt = ktbeg; kt < ktend; kt++) {
            const int jbase = kt * 64;
            const bool more = (kt + 1 < ktend);
            float* Ksf = sm + cur * KVBUF;
            float* Vsf = Ksf + 64 * FSTR;

            // prefetch next tile (overlaps compute)
            if (more) {
                #pragma unroll
                for (int i = 0; i < 8; i++) {
                    const int j = jj0 + i * 8;
                    const size_t g = base + (size_t)((kt + 1) * 64 + j) * HH + hh0;
                    pk[i] = *(const float4*)&g_K[g];
                    pv[i] = *(const float4*)&g_V[g];
                }
            }

            // ---- S = Q K^T ----
            float sS[8][4];
            #pragma unroll
            for (int nb = 0; nb < 8; nb++)
                sS[nb][0] = sS[nb][1] = sS[nb][2] = sS[nb][3] = 0.0f;
            #pragma unroll
            for (int nb = 0; nb < 8; nb++)
                #pragma unroll
                for (int kb = 0; kb < 8; kb++) {
                    float2 t = *(const float2*)&Ksf[(kb * 8 + nb) * FSTR + l * 2];
                    mma_tf32(sS[nb], qf[kb], __float_as_uint(t.x), __float_as_uint(t.y));
                }

            if (kt == qt) {
                #pragma unroll
                for (int nb = 0; nb < 8; nb++) {
                    const int col = jbase + nb * 8 + 2 * c;
                    if (col     > rowg ) sS[nb][0] = -1.0e30f;
                    if (col + 1 > rowg ) sS[nb][1] = -1.0e30f;
                    if (col     > rowg8) sS[nb][2] = -1.0e30f;
                    if (col + 1 > rowg8) sS[nb][3] = -1.0e30f;
                }
            }

            // ---- online softmax ----
            float mx0 = -1.0e30f, mx1 = -1.0e30f;
            #pragma unroll
            for (int nb = 0; nb < 8; nb++) {
                mx0 = fmaxf(mx0, fmaxf(sS[nb][0], sS[nb][1]));
                mx1 = fmaxf(mx1, fmaxf(sS[nb][2], sS[nb][3]));
            }
            mx0 = fmaxf(mx0, __shfl_xor_sync(0xffffffffu, mx0, 1));
            mx0 = fmaxf(mx0, __shfl_xor_sync(0xffffffffu, mx0, 2));
            mx1 = fmaxf(mx1, __shfl_xor_sync(0xffffffffu, mx1, 1));
            mx1 = fmaxf(mx1, __shfl_xor_sync(0xffffffffu, mx1, 2));

            const float nm0 = fmaxf(mR, mx0);
            const float nm1 = fmaxf(mR8, mx1);
            const float corr0 = __expf(mR - nm0);
            const float corr1 = __expf(mR8 - nm1);

            float sum0 = 0.0f, sum1 = 0.0f;
            #pragma unroll
            for (int nb = 0; nb < 8; nb++) {
                sS[nb][0] = __expf(sS[nb][0] - nm0);
                sS[nb][1] = __expf(sS[nb][1] - nm0);
                sS[nb][2] = __expf(sS[nb][2] - nm1);
                sS[nb][3] = __expf(sS[nb][3] - nm1);
                sum0 += sS[nb][0] + sS[nb][1];
                sum1 += sS[nb][2] + sS[nb][3];
                *(float2*)&Ps[(w * 16 + r    ) * PSTR + nb * 8 + 2 * c] =
                    make_float2(sS[nb][0], sS[nb][1]);
                *(float2*)&Ps[(w * 16 + r + 8) * PSTR + nb * 8 + 2 * c] =
                    make_float2(sS[nb][2], sS[nb][3]);
            }
            sum0 += __shfl_xor_sync(0xffffffffu, sum0, 1);
            sum0 += __shfl_xor_sync(0xffffffffu, sum0, 2);
            sum1 += __shfl_xor_sync(0xffffffffu, sum1, 1);
            sum1 += __shfl_xor_sync(0xffffffffu, sum1, 2);

            lR  = lR  * corr0 + sum0;  mR  = nm0;
            lR8 = lR8 * corr1 + sum1;  mR8 = nm1;
            #pragma unroll
            for (int hb = 0; hb < 8; hb++) {
                o[hb][0] *= corr0; o[hb][1] *= corr0;
                o[hb][2] *= corr1; o[hb][3] *= corr1;
            }
            __syncwarp();   // Ps rows are warp-private

            // ---- O += P @ V ----
            #pragma unroll
            for (int kb = 0; kb < 8; kb++) {
                uint32_t a[4];
                a[0] = __float_as_uint(Ps[(w * 16 + r    ) * PSTR + kb * 8 + c]);
                a[1] = __float_as_uint(Ps[(w * 16 + r + 8) * PSTR + kb * 8 + c]);
                a[2] = __float_as_uint(Ps[(w * 16 + r    ) * PSTR + kb * 8 + c + 4]);
                a[3] = __float_as_uint(Ps[(w * 16 + r + 8) * PSTR + kb * 8 + c + 4]);
                #pragma unroll
                for (int hb = 0; hb < 8; hb++) {
                    float2 t = *(const float2*)&Vsf[(kb * 8 + hb) * FSTR + l * 2];
                    mma_tf32(o[hb], a, __float_as_uint(t.x), __float_as_uint(t.y));
                }
            }

            // ---- stage next tile into the other buffer; ONE sync per tile ----
            if (more) {
                float* Kn = sm + (cur ^ 1) * KVBUF;
                stage_kv(Kn, Kn + 64 * FSTR, pk, pv, jj0, hh0);
                __syncthreads();
            }
            cur ^= 1;
        }
    }

    // store partials (unconditionally; empty split stores zeros with weight 0)
    const size_t pr  = (size_t)(s * BB + b) * TT + rowg;
    const size_t pr8 = pr + 8;
    #pragma unroll
    for (int hb = 0; hb < 8; hb++) {
        *(float2*)&g_pO[pr  * HH + hb * 8 + 2 * c] = make_float2(o[hb][0], o[hb][1]);
        *(float2*)&g_pO[pr8 * HH + hb * 8 + 2 * c] = make_float2(o[hb][2], o[hb][3]);
    }
    if (c == 0) {
        g_pm[pr]  = mR;   g_pl[pr]  = lR;
        g_pm[pr8] = mR8;  g_pl[pr8] = lR8;
    }
}

// ---------------------------------------------------------------------------
// Kernel 3: merge the four kv-splits.
// ---------------------------------------------------------------------------
__global__ __launch_bounds__(256) void combine_kernel(float* __restrict__ out)
{
    const int gid  = blockIdx.x * 256 + threadIdx.x;
    const int rowg = gid >> 4;
    const int col  = (gid & 15) * 4;

    float mv[NSPLIT], lv[NSPLIT];
    float M = -1.0e30f;
    #pragma unroll
    for (int sp = 0; sp < NSPLIT; sp++) {
        mv[sp] = g_pm[sp * BT + rowg];
        lv[sp] = g_pl[sp * BT + rowg];
        M = fmaxf(M, mv[sp]);
    }
    float denom = 0.0f;
    float a[NSPLIT];
    #pragma unroll
    for (int sp = 0; sp < NSPLIT; sp++) {
        a[sp] = __expf(mv[sp] - M);
        denom += lv[sp] * a[sp];
    }
    const float inv = 1.0f / denom;

    float4 acc = make_float4(0.f, 0.f, 0.f, 0.f);
    #pragma unroll
    for (int sp = 0; sp < NSPLIT; sp++) {
        float4 O = *(const float4*)&g_pO[((size_t)sp * BT + rowg) * HH + col];
        acc.x += O.x * a[sp];
        acc.y += O.y * a[sp];
        acc.z += O.z * a[sp];
        acc.w += O.w * a[sp];
    }
    acc.x *= inv; acc.y *= inv; acc.z *= inv; acc.w *= inv;
    *(float4*)&out[(size_t)rowg * HH + col] = acc;
}

// ---------------------------------------------------------------------------
extern "C" void kernel_launch(void* const* d_in, const int* in_sizes, int n_in,
                              void* d_out, int out_size)
{
    const float* x  = (const float*)d_in[0];
    const float* Wq = (const float*)d_in[1];
    const float* Wk = (const float*)d_in[2];
    const float* Wv = (const float*)d_in[3];
    float* out = (float*)d_out;

    const int attn_smem = (2 * KVBUF + 64 * PSTR) * sizeof(float);  // ~85 KB
    cudaFuncSetAttribute(attn_kernel, cudaFuncAttributeMaxDynamicSharedMemorySize,
                         attn_smem);

    prep_w<<<(DD * 192 + 255) / 256, 256>>>(Wq, Wk, Wv);
    qkv_mma<<<(BT / 128) * 2, 256>>>(x);
    attn_kernel<<<64 * BB * NSPLIT, 128, attn_smem>>>();
    combine_kernel<<<(BT * HH / 4) / 256, 256>>>(out);
}

// round 8
// speedup vs baseline: 1.1721x; 1.1721x over previous
#include <cuda_runtime.h>
#include <cuda_bf16.h>
#include <cstdint>

#define BB 4
#define TT 4096
#define DD 768
#define HH 64
#define BT (BB*TT)
#define NSPLIT 4

// Scratch. g_Q: pre-scaled (x0.125) + tf32-rna-rounded. g_K: tf32-rna-rounded.
// g_Vt: V transposed, layout [b][h][t].
__device__ float  g_Q[BT * HH];
__device__ float  g_K[BT * HH];
__device__ float  g_Vt[BB * HH * TT];
__device__ float2 g_Wsp[DD * 192];          // W (Q|K|V) split into (tf32 hi, lo)
__device__ float  g_pO[NSPLIT * BT * HH];   // split-kv partial O (unnormalized)
__device__ float  g_pm[NSPLIT * BT];
__device__ float  g_pl[NSPLIT * BT];

// ---------------------------------------------------------------------------
// helpers
// ---------------------------------------------------------------------------
__device__ __forceinline__ uint32_t f2tf(float f) {
    uint32_t u;
    asm("cvt.rna.tf32.f32 %0, %1;" : "=r"(u) : "f"(f));
    return u;
}
__device__ __forceinline__ float tf32f(float f) {
    return __uint_as_float(f2tf(f));
}

__device__ __forceinline__ void mma_tf32(float d[4], const uint32_t a[4],
                                         uint32_t b0, uint32_t b1) {
    asm volatile(
        "mma.sync.aligned.m16n8k8.row.col.f32.tf32.tf32.f32 "
        "{%0,%1,%2,%3}, {%4,%5,%6,%7}, {%8,%9}, {%0,%1,%2,%3};"
        : "+f"(d[0]), "+f"(d[1]), "+f"(d[2]), "+f"(d[3])
        : "r"(a[0]), "r"(a[1]), "r"(a[2]), "r"(a[3]), "r"(b0), "r"(b1));
}

__device__ __forceinline__ void cpa16(uint32_t smem_dst, const void* gsrc) {
    asm volatile("cp.async.cg.shared.global [%0], [%1], 16;"
                 :: "r"(smem_dst), "l"(gsrc));
}
__device__ __forceinline__ void cpa_commit() {
    asm volatile("cp.async.commit_group;");
}
__device__ __forceinline__ void cpa_wait0() {
    asm volatile("cp.async.wait_group 0;" ::: "memory");
}

// ---------------------------------------------------------------------------
// Kernel 0: split W = [Wq|Wk|Wv] into (hi, lo) tf32 pair.
// ---------------------------------------------------------------------------
__global__ __launch_bounds__(256) void prep_w(
    const float* __restrict__ Wq, const float* __restrict__ Wk,
    const float* __restrict__ Wv)
{
    int i = blockIdx.x * 256 + threadIdx.x;
    if (i >= DD * 192) return;
    int k = i / 192, n = i % 192;
    float v = (n < 64) ? Wq[k * 64 + n]
            : (n < 128) ? Wk[k * 64 + n - 64]
            : Wv[k * 64 + n - 128];
    float hi = tf32f(v);
    float lo = tf32f(v - hi);
    g_Wsp[i] = make_float2(hi, lo);
}

// ---------------------------------------------------------------------------
// Kernel 1: QKV projection, tensor cores, 3-term tf32 split, sw-pipelined.
// Epilogue: Q pre-scaled+rounded, K rounded, V stored transposed [b][h][t].
// ---------------------------------------------------------------------------
__global__ __launch_bounds__(256) void qkv_mma(const float* __restrict__ x)
{
    __shared__ float  xs[128 * 36];
    __shared__ float4 wf[4 * 12 * 33];

    const int tid = threadIdx.x;
    const int w   = tid >> 5;
    const int l   = tid & 31;
    const int mg  = w >> 1;
    const int ng  = w & 1;
    const int row0 = (blockIdx.x >> 1) * 128;
    const int n0   = (blockIdx.x & 1) * 96;

    float acc[2][6][4];
    #pragma unroll
    for (int mt = 0; mt < 2; mt++)
        #pragma unroll
        for (int nb = 0; nb < 6; nb++)
            acc[mt][nb][0] = acc[mt][nb][1] = acc[mt][nb][2] = acc[mt][nb][3] = 0.0f;

    float4 px[4];
    float2 pw[12];

    #pragma unroll
    for (int t = 0; t < 4; t++) {
        int f  = tid + t * 256;
        int r  = f >> 3;
        int c4 = (f & 7) * 4;
        px[t] = *(const float4*)&x[(size_t)(row0 + r) * DD + c4];
    }
    #pragma unroll
    for (int t = 0; t < 12; t++) {
        int i  = tid + t * 256;
        int kk = i / 96;
        int nn = i % 96;
        pw[t] = g_Wsp[(size_t)kk * 192 + n0 + nn];
    }

    for (int k0 = 0; k0 < DD; k0 += 32) {
        #pragma unroll
        for (int t = 0; t < 4; t++) {
            int f  = tid + t * 256;
            int r  = f >> 3;
            int c4 = (f & 7) * 4;
            *(float4*)&xs[r * 36 + c4] = px[t];
        }
        #pragma unroll
        for (int t = 0; t < 12; t++) {
            int i  = tid + t * 256;
            int kk = i / 96;
            int nn = i % 96;
            int kb   = kk >> 3, kr = kk & 7;
            int slot = kr >> 2;
            int nb   = nn >> 3;
            int lane = ((nn & 7) << 2) | (kr & 3);
            float* p = (float*)&wf[(kb * 12 + nb) * 33 + lane];
            p[slot]     = pw[t].x;
            p[2 + slot] = pw[t].y;
        }
        __syncthreads();

        if (k0 + 32 < DD) {
            #pragma unroll
            for (int t = 0; t < 4; t++) {
                int f  = tid + t * 256;
                int r  = f >> 3;
                int c4 = (f & 7) * 4;
                px[t] = *(const float4*)&x[(size_t)(row0 + r) * DD + k0 + 32 + c4];
            }
            #pragma unroll
            for (int t = 0; t < 12; t++) {
                int i  = tid + t * 256;
                int kk = i / 96;
                int nn = i % 96;
                pw[t] = g_Wsp[(size_t)(k0 + 32 + kk) * 192 + n0 + nn];
            }
        }

        #pragma unroll
        for (int kb = 0; kb < 4; kb++) {
            uint32_t ahi[2][4], alo[2][4];
            #pragma unroll
            for (int mt = 0; mt < 2; mt++) {
                const int rA = mg * 32 + mt * 16 + (l >> 2);
                const int cA = kb * 8 + (l & 3);
                float a0 = xs[rA * 36 + cA];
                float a1 = xs[(rA + 8) * 36 + cA];
                float a2 = xs[rA * 36 + cA + 4];
                float a3 = xs[(rA + 8) * 36 + cA + 4];
                ahi[mt][0] = f2tf(a0); alo[mt][0] = f2tf(a0 - __uint_as_float(ahi[mt][0]));
                ahi[mt][1] = f2tf(a1); alo[mt][1] = f2tf(a1 - __uint_as_float(ahi[mt][1]));
                ahi[mt][2] = f2tf(a2); alo[mt][2] = f2tf(a2 - __uint_as_float(ahi[mt][2]));
                ahi[mt][3] = f2tf(a3); alo[mt][3] = f2tf(a3 - __uint_as_float(ahi[mt][3]));
            }
            #pragma unroll
            for (int nb = 0; nb < 6; nb++) {
                float4 q = wf[(kb * 12 + ng * 6 + nb) * 33 + l];
                uint32_t bh0 = __float_as_uint(q.x), bh1 = __float_as_uint(q.y);
                uint32_t bl0 = __float_as_uint(q.z), bl1 = __float_as_uint(q.w);
                #pragma unroll
                for (int mt = 0; mt < 2; mt++) {
                    mma_tf32(acc[mt][nb], ahi[mt], bh0, bh1);
                    mma_tf32(acc[mt][nb], ahi[mt], bl0, bl1);
                    mma_tf32(acc[mt][nb], alo[mt], bh0, bh1);
                }
            }
        }
        __syncthreads();
    }

    #pragma unroll
    for (int mt = 0; mt < 2; mt++) {
        #pragma unroll
        for (int nb = 0; nb < 6; nb++) {
            const int rowa  = row0 + mg * 32 + mt * 16 + (l >> 2);
            const int nglob = n0 + ng * 48 + nb * 8 + (l & 3) * 2;
            const int mat   = nglob >> 6;
            const int col   = nglob & 63;
            if (mat == 0) {
                // Q: pre-scale by 1/8 and tf32-round (rna(0.125*q) == 0.125*rna(q))
                *(float2*)&g_Q[(size_t)rowa * HH + col] =
                    make_float2(tf32f(0.125f * acc[mt][nb][0]),
                                tf32f(0.125f * acc[mt][nb][1]));
                *(float2*)&g_Q[(size_t)(rowa + 8) * HH + col] =
                    make_float2(tf32f(0.125f * acc[mt][nb][2]),
                                tf32f(0.125f * acc[mt][nb][3]));
            } else if (mat == 1) {
                // K: tf32-round
                *(float2*)&g_K[(size_t)rowa * HH + col] =
                    make_float2(tf32f(acc[mt][nb][0]), tf32f(acc[mt][nb][1]));
                *(float2*)&g_K[(size_t)(rowa + 8) * HH + col] =
                    make_float2(tf32f(acc[mt][nb][2]), tf32f(acc[mt][nb][3]));
            } else {
                // V: transposed store [b][h][t]; b = rowa>>12, t = rowa&4095
                const int bb = rowa >> 12;
                const int t0 = rowa & 4095;
                g_Vt[((size_t)(bb << 6) + col    ) * TT + t0    ] = acc[mt][nb][0];
                g_Vt[((size_t)(bb << 6) + col + 1) * TT + t0    ] = acc[mt][nb][1];
                g_Vt[((size_t)(bb << 6) + col    ) * TT + t0 + 8] = acc[mt][nb][2];
                g_Vt[((size_t)(bb << 6) + col + 1) * TT + t0 + 8] = acc[mt][nb][3];
            }
        }
    }
}

// ---------------------------------------------------------------------------
// Kernel 2: causal flash attention, tensor cores, split-kv (4).
// cp.async double-buffered raw K / Vt tiles (chunk-XOR swizzle),
// conflict-free LDS.32 B-fragments, P exchange via shfl (no Ps smem).
// smem = 64 KB, ~140 regs -> 3 CTAs/SM.
// ---------------------------------------------------------------------------
__global__ __launch_bounds__(128, 3) void attn_kernel()
{
    extern __shared__ float sm[];   // [buf][K 4096 | Vt 4096] floats

    const int tid = threadIdx.x;
    const int w   = tid >> 5;
    const int l   = tid & 31;
    const int r   = l >> 2;          // row-in-group 0..7
    const int c   = l & 3;

    const int bid = blockIdx.x;
    const int qt  = 63 - (bid >> 4);
    const int b   = (bid >> 2) & 3;
    const int s   = bid & 3;
    const int q0  = qt * 64;
    const size_t base = (size_t)b * TT * HH;

    const int nt    = qt + 1;
    const int chunk = (nt + NSPLIT - 1) >> 2;
    const int ktbeg = min(s * chunk, nt);
    const int ktend = min(ktbeg + chunk, nt);

    const int rowg  = q0 + w * 16 + r;
    const int rowg8 = rowg + 8;

    float o[8][4];
    #pragma unroll
    for (int hb = 0; hb < 8; hb++)
        o[hb][0] = o[hb][1] = o[hb][2] = o[hb][3] = 0.0f;
    float mR = -1.0e30f, mR8 = -1.0e30f, lR = 0.0f, lR8 = 0.0f;

    if (ktbeg < ktend) {
        const uint32_t sb = (uint32_t)__cvta_generic_to_shared(sm);

        // staging coords for cp.async (per-thread 8 chunks each for K and V)
        const int crow = tid >> 4;       // 0..7 (+8i)
        const int cq   = tid & 15;       // 16B chunk within row

        // Q fragments (already scaled+rounded in gmem)
        uint32_t qf[8][4];
        #pragma unroll
        for (int kb = 0; kb < 8; kb++) {
            qf[kb][0] = __float_as_uint(g_Q[base + (size_t)rowg  * HH + kb * 8 + c]);
            qf[kb][1] = __float_as_uint(g_Q[base + (size_t)rowg8 * HH + kb * 8 + c]);
            qf[kb][2] = __float_as_uint(g_Q[base + (size_t)rowg  * HH + kb * 8 + c + 4]);
            qf[kb][3] = __float_as_uint(g_Q[base + (size_t)rowg8 * HH + kb * 8 + c + 4]);
        }

        // issue tile loads into buffer `bf`
        auto issue = [&](int bf, int jb) {
            #pragma unroll
            for (int i = 0; i < 8; i++) {
                const int row = crow + i * 8;
                const uint32_t swz = (uint32_t)((cq ^ (row & 7)) << 4);
                // K[j][h]
                cpa16(sb + (uint32_t)bf * 32768u + (uint32_t)row * 256u + swz,
                      &g_K[base + (size_t)(jb + row) * HH + cq * 4]);
                // Vt[h][t]
                cpa16(sb + (uint32_t)bf * 32768u + 16384u + (uint32_t)row * 256u + swz,
                      &g_Vt[((size_t)(b << 6) + row) * TT + jb + cq * 4]);
            }
            cpa_commit();
        };

        issue(0, ktbeg * 64);

        int cur = 0;
        const int qs1 = (l & 28) | (c >> 1);
        const int qs2 = qs1 + 2;

        for (int kt = ktbeg; kt < ktend; kt++) {
            const int jbase = kt * 64;
            cpa_wait0();
            __syncthreads();            // tile cur ready; prev compute done
            if (kt + 1 < ktend) issue(cur ^ 1, jbase + 64);

            const float* kp = sm + cur * 8192;
            const float* vp = kp + 4096;

            // ---- S = Q K^T ----
            float sS[8][4];
            #pragma unroll
            for (int nb = 0; nb < 8; nb++)
                sS[nb][0] = sS[nb][1] = sS[nb][2] = sS[nb][3] = 0.0f;
            #pragma unroll
            for (int nb = 0; nb < 8; nb++) {
                const float* rowp = kp + (nb * 8 + r) * 64;
                #pragma unroll
                for (int kb = 0; kb < 8; kb++) {
                    float b0 = rowp[(((kb * 2)     ^ r) << 2) + c];
                    float b1 = rowp[(((kb * 2 + 1) ^ r) << 2) + c];
                    mma_tf32(sS[nb], qf[kb],
                             __float_as_uint(b0), __float_as_uint(b1));
                }
            }

            if (kt == qt) {
                #pragma unroll
                for (int nb = 0; nb < 8; nb++) {
                    const int col = jbase + nb * 8 + 2 * c;
                    if (col     > rowg ) sS[nb][0] = -1.0e30f;
                    if (col + 1 > rowg ) sS[nb][1] = -1.0e30f;
                    if (col     > rowg8) sS[nb][2] = -1.0e30f;
                    if (col + 1 > rowg8) sS[nb][3] = -1.0e30f;
                }
            }

            // ---- online softmax ----
            float mx0 = -1.0e30f, mx1 = -1.0e30f;
            #pragma unroll
            for (int nb = 0; nb < 8; nb++) {
                mx0 = fmaxf(mx0, fmaxf(sS[nb][0], sS[nb][1]));
                mx1 = fmaxf(mx1, fmaxf(sS[nb][2], sS[nb][3]));
            }
            mx0 = fmaxf(mx0, __shfl_xor_sync(0xffffffffu, mx0, 1));
            mx0 = fmaxf(mx0, __shfl_xor_sync(0xffffffffu, mx0, 2));
            mx1 = fmaxf(mx1, __shfl_xor_sync(0xffffffffu, mx1, 1));
            mx1 = fmaxf(mx1, __shfl_xor_sync(0xffffffffu, mx1, 2));

            const float nm0 = fmaxf(mR, mx0);
            const float nm1 = fmaxf(mR8, mx1);
            const float corr0 = __expf(mR - nm0);
            const float corr1 = __expf(mR8 - nm1);

            float sum0 = 0.0f, sum1 = 0.0f;
            #pragma unroll
            for (int nb = 0; nb < 8; nb++) {
                sS[nb][0] = __expf(sS[nb][0] - nm0);
                sS[nb][1] = __expf(sS[nb][1] - nm0);
                sS[nb][2] = __expf(sS[nb][2] - nm1);
                sS[nb][3] = __expf(sS[nb][3] - nm1);
                sum0 += sS[nb][0] + sS[nb][1];
                sum1 += sS[nb][2] + sS[nb][3];
            }
            sum0 += __shfl_xor_sync(0xffffffffu, sum0, 1);
            sum0 += __shfl_xor_sync(0xffffffffu, sum0, 2);
            sum1 += __shfl_xor_sync(0xffffffffu, sum1, 1);
            sum1 += __shfl_xor_sync(0xffffffffu, sum1, 2);

            lR  = lR  * corr0 + sum0;  mR  = nm0;
            lR8 = lR8 * corr1 + sum1;  mR8 = nm1;
            #pragma unroll
            for (int hb = 0; hb < 8; hb++) {
                o[hb][0] *= corr0; o[hb][1] *= corr0;
                o[hb][2] *= corr1; o[hb][3] *= corr1;
            }

            // ---- O += P @ V  (P exchanged via shfl into A-fragments) ----
            #pragma unroll
            for (int kb = 0; kb < 8; kb++) {
                float e, od;
                uint32_t a[4];
                e  = __shfl_sync(0xffffffffu, sS[kb][0], qs1);
                od = __shfl_sync(0xffffffffu, sS[kb][1], qs1);
                a[0] = __float_as_uint((c & 1) ? od : e);
                e  = __shfl_sync(0xffffffffu, sS[kb][2], qs1);
                od = __shfl_sync(0xffffffffu, sS[kb][3], qs1);
                a[1] = __float_as_uint((c & 1) ? od : e);
                e  = __shfl_sync(0xffffffffu, sS[kb][0], qs2);
                od = __shfl_sync(0xffffffffu, sS[kb][1], qs2);
                a[2] = __float_as_uint((c & 1) ? od : e);
                e  = __shfl_sync(0xffffffffu, sS[kb][2], qs2);
                od = __shfl_sync(0xffffffffu, sS[kb][3], qs2);
                a[3] = __float_as_uint((c & 1) ? od : e);

                #pragma unroll
                for (int hb = 0; hb < 8; hb++) {
                    const float* rowp = vp + (hb * 8 + r) * 64;
                    float b0 = rowp[(((kb * 2)     ^ r) << 2) + c];
                    float b1 = rowp[(((kb * 2 + 1) ^ r) << 2) + c];
                    mma_tf32(o[hb], a, __float_as_uint(b0), __float_as_uint(b1));
                }
            }
            cur ^= 1;
        }
    }

    // store partials (empty split stores zeros with weight l=0)
    const size_t pr  = (size_t)(s * BB + b) * TT + rowg;
    const size_t pr8 = pr + 8;
    #pragma unroll
    for (int hb = 0; hb < 8; hb++) {
        *(float2*)&g_pO[pr  * HH + hb * 8 + 2 * c] = make_float2(o[hb][0], o[hb][1]);
        *(float2*)&g_pO[pr8 * HH + hb * 8 + 2 * c] = make_float2(o[hb][2], o[hb][3]);
    }
    if (c == 0) {
        g_pm[pr]  = mR;   g_pl[pr]  = lR;
        g_pm[pr8] = mR8;  g_pl[pr8] = lR8;
    }
}

// ---------------------------------------------------------------------------
// Kernel 3: merge the four kv-splits.
// ---------------------------------------------------------------------------
__global__ __launch_bounds__(256) void combine_kernel(float* __restrict__ out)
{
    const int gid  = blockIdx.x * 256 + threadIdx.x;
    const int rowg = gid >> 4;
    const int col  = (gid & 15) * 4;

    float mv[NSPLIT], lv[NSPLIT];
    float M = -1.0e30f;
    #pragma unroll
    for (int sp = 0; sp < NSPLIT; sp++) {
        mv[sp] = g_pm[sp * BT + rowg];
        lv[sp] = g_pl[sp * BT + rowg];
        M = fmaxf(M, mv[sp]);
    }
    float denom = 0.0f;
    float a[NSPLIT];
    #pragma unroll
    for (int sp = 0; sp < NSPLIT; sp++) {
        a[sp] = __expf(mv[sp] - M);
        denom += lv[sp] * a[sp];
    }
    const float inv = 1.0f / denom;

    float4 acc = make_float4(0.f, 0.f, 0.f, 0.f);
    #pragma unroll
    for (int sp = 0; sp < NSPLIT; sp++) {
        float4 O = *(const float4*)&g_pO[((size_t)sp * BT + rowg) * HH + col];
        acc.x += O.x * a[sp];
        acc.y += O.y * a[sp];
        acc.z += O.z * a[sp];
        acc.w += O.w * a[sp];
    }
    acc.x *= inv; acc.y *= inv; acc.z *= inv; acc.w *= inv;
    *(float4*)&out[(size_t)rowg * HH + col] = acc;
}

// ---------------------------------------------------------------------------
extern "C" void kernel_launch(void* const* d_in, const int* in_sizes, int n_in,
                              void* d_out, int out_size)
{
    const float* x  = (const float*)d_in[0];
    const float* Wq = (const float*)d_in[1];
    const float* Wk = (const float*)d_in[2];
    const float* Wv = (const float*)d_in[3];
    float* out = (float*)d_out;

    const int attn_smem = 2 * 2 * 4096 * sizeof(float);   // 64 KB
    cudaFuncSetAttribute(attn_kernel, cudaFuncAttributeMaxDynamicSharedMemorySize,
                         attn_smem);

    prep_w<<<(DD * 192 + 255) / 256, 256>>>(Wq, Wk, Wv);
    qkv_mma<<<(BT / 128) * 2, 256>>>(x);
    attn_kernel<<<64 * BB * NSPLIT, 128, attn_smem>>>();
    combine_kernel<<<(BT * HH / 4) / 256, 256>>>(out);
}